// round 14
// baseline (speedup 1.0000x reference)
#include <cuda_runtime.h>
#include <cuda_bf16.h>
#include <math_constants.h>

#define B_ 8
#define T_ 2048
#define C_ 1024
#define H_ 64
#define M_ (B_*T_)

// Packed bf16 hi/lo pairs (u32 = two bf16 along the mma k-dim).
// Q,K: [M][32] pairs along h.  V: transposed [H][M/2] pairs along key index.
__device__ unsigned g_qrh[M_*32], g_qrl[M_*32], g_qih[M_*32], g_qil[M_*32];
__device__ unsigned g_krh[M_*32], g_krl[M_*32], g_kih[M_*32], g_kil[M_*32];
__device__ unsigned g_vrh[(size_t)H_*(M_/2)], g_vrl[(size_t)H_*(M_/2)];
__device__ unsigned g_vih[(size_t)H_*(M_/2)], g_vil[(size_t)H_*(M_/2)];

__device__ __forceinline__ unsigned pkbf2(float lo, float hi) {
    unsigned r; asm("cvt.rn.bf16x2.f32 %0, %1, %2;" : "=r"(r) : "f"(hi), "f"(lo));
    return r;
}
__device__ __forceinline__ void split1(float x, float& h, float& l) {
    h = __bfloat162float(__float2bfloat16(x));
    l = x - h;
}
__device__ __forceinline__ void mma16(float* d, const unsigned* a, const unsigned* b) {
    asm volatile("mma.sync.aligned.m16n8k16.row.col.f32.bf16.bf16.f32 "
        "{%0,%1,%2,%3}, {%4,%5,%6,%7}, {%8,%9}, {%0,%1,%2,%3};"
        : "+f"(d[0]), "+f"(d[1]), "+f"(d[2]), "+f"(d[3])
        : "r"(a[0]), "r"(a[1]), "r"(a[2]), "r"(a[3]), "r"(b[0]), "r"(b[1]));
}
__device__ __forceinline__ unsigned smem_u32(const void* p) {
    unsigned a;
    asm("{ .reg .u64 t; cvta.to.shared.u64 t, %1; cvt.u32.u64 %0, t; }"
        : "=r"(a) : "l"(p));
    return a;
}
__device__ __forceinline__ void cpa16(unsigned saddr, const void* g) {
    asm volatile("cp.async.cg.shared.global [%0], [%1], 16;"
                 :: "r"(saddr), "l"(g) : "memory");
}
#define CP_COMMIT() asm volatile("cp.async.commit_group;" ::: "memory")
#define CP_WAIT1()  asm volatile("cp.async.wait_group 1;" ::: "memory")
#define CP_WAIT0()  asm volatile("cp.async.wait_group 0;" ::: "memory")

// ===========================================================================
// Projection (unchanged, R13): bf16-split HMMA, scalar split staging.
// CTA = 128 rows x 64 cols of ONE matrix. Epilogue pre-packs hi/lo pairs.
// ===========================================================================
#define PJ_AB0 0
#define PJ_BB0 10240
#define PJ_U32 15360

__global__ __launch_bounds__(256, 2) void proj_kernel(
    const float* __restrict__ xr,  const float* __restrict__ xi,
    const float* __restrict__ Wkr, const float* __restrict__ Wki,
    const float* __restrict__ Wqr, const float* __restrict__ Wqi,
    const float* __restrict__ Wvr, const float* __restrict__ Wvi)
{
    extern __shared__ unsigned smu[];
    unsigned* As = smu + PJ_AB0;
    unsigned* Bs = smu + PJ_BB0;

    const int tid  = threadIdx.x;
    const int lane = tid & 31;
    const int w    = tid >> 5;
    const int wm   = w >> 1;
    const int wn   = w & 1;
    const int g    = lane >> 2;
    const int kl   = lane & 3;

    const int rt  = blockIdx.x / 3;
    const int mat = blockIdx.x % 3;   // 0=K 1=Q 2=V
    const int m0  = rt * 128;

    const float* Wr_ = (mat==0)? Wkr : (mat==1)? Wqr : Wvr;
    const float* Wi_ = (mat==0)? Wki : (mat==1)? Wqi : Wvi;

    float dR[2][4][4], dI[2][4][4];
    #pragma unroll
    for (int mt=0; mt<2; ++mt)
        #pragma unroll
        for (int nt=0; nt<4; ++nt)
            #pragma unroll
            for (int r=0; r<4; ++r) { dR[mt][nt][r]=0.f; dI[mt][nt][r]=0.f; }

    const int a_ri = tid >> 7;
    const int a_m  = tid & 127;
    const float* a_src = (a_ri ? xi : xr) + (size_t)(m0 + a_m)*C_;
    unsigned* a_h = As + (a_ri*2    )*2560 + a_m*20;
    unsigned* a_l = As + (a_ri*2 + 1)*2560 + a_m*20;
    const int b_n  = tid & 63;
    const int b_kq = tid >> 6;

    for (int c0 = 0; c0 < C_; c0 += 32) {
        __syncthreads();
        #pragma unroll
        for (int j = 0; j < 8; ++j) {
            float4 v = *(const float4*)(a_src + c0 + j*4);
            float h0,l0,h1,l1,h2,l2,h3,l3;
            split1(v.x,h0,l0); split1(v.y,h1,l1);
            split1(v.z,h2,l2); split1(v.w,h3,l3);
            a_h[j*2  ] = pkbf2(h0,h1);
            a_h[j*2+1] = pkbf2(h2,h3);
            a_l[j*2  ] = pkbf2(l0,l1);
            a_l[j*2+1] = pkbf2(l2,l3);
        }
        #pragma unroll
        for (int jj = 0; jj < 4; ++jj) {
            const int k2 = jj*4 + b_kq;
            const size_t krow = (size_t)(c0 + 2*k2);
            float wr0 = Wr_[krow*H_ + b_n], wr1 = Wr_[(krow+1)*H_ + b_n];
            float wi0 = Wi_[krow*H_ + b_n], wi1 = Wi_[(krow+1)*H_ + b_n];
            float h0,l0,h1,l1,h2,l2,h3,l3;
            split1(wr0,h0,l0); split1(wr1,h1,l1);
            split1(wi0,h2,l2); split1(wi1,h3,l3);
            Bs[0*1280 + b_n*20 + k2] = pkbf2(h0,h1);
            Bs[1*1280 + b_n*20 + k2] = pkbf2(l0,l1);
            Bs[2*1280 + b_n*20 + k2] = pkbf2(h2,h3);
            Bs[3*1280 + b_n*20 + k2] = pkbf2(l2,l3);
        }
        __syncthreads();

        #pragma unroll
        for (int ks = 0; ks < 2; ++ks) {
            const int pb = ks*8;
            #pragma unroll
            for (int mt = 0; mt < 2; ++mt) {
                const int mrow = wm*32 + mt*16 + g;
                unsigned frh[4], frl[4], fih[4], fil[4];
                #pragma unroll
                for (int q = 0; q < 4; ++q) {
                    const int rr = mrow + ((q & 1) ? 8 : 0);
                    const int cc = pb + kl + ((q >> 1) ? 4 : 0);
                    frh[q] = As[0*2560 + rr*20 + cc];
                    frl[q] = As[1*2560 + rr*20 + cc];
                    fih[q] = As[2*2560 + rr*20 + cc];
                    fil[q] = As[3*2560 + rr*20 + cc];
                }
                #pragma unroll
                for (int nt = 0; nt < 4; ++nt) {
                    const int n0 = wn*32 + nt*8 + g;
                    unsigned brh[2], brl[2], bih[2], bil[2], nih[2], nil_[2];
                    brh[0]=Bs[0*1280 + n0*20 + pb+kl];
                    brh[1]=Bs[0*1280 + n0*20 + pb+kl+4];
                    brl[0]=Bs[1*1280 + n0*20 + pb+kl];
                    brl[1]=Bs[1*1280 + n0*20 + pb+kl+4];
                    bih[0]=Bs[2*1280 + n0*20 + pb+kl];
                    bih[1]=Bs[2*1280 + n0*20 + pb+kl+4];
                    bil[0]=Bs[3*1280 + n0*20 + pb+kl];
                    bil[1]=Bs[3*1280 + n0*20 + pb+kl+4];
                    nih[0]=bih[0]^0x80008000u; nih[1]=bih[1]^0x80008000u;
                    nil_[0]=bil[0]^0x80008000u; nil_[1]=bil[1]^0x80008000u;
                    mma16(dR[mt][nt], frh, brh);
                    mma16(dR[mt][nt], frh, brl);
                    mma16(dR[mt][nt], frl, brh);
                    mma16(dR[mt][nt], fih, nih);
                    mma16(dR[mt][nt], fih, nil_);
                    mma16(dR[mt][nt], fil, nih);
                    mma16(dI[mt][nt], fih, brh);
                    mma16(dI[mt][nt], fih, brl);
                    mma16(dI[mt][nt], fil, brh);
                    mma16(dI[mt][nt], frh, bih);
                    mma16(dI[mt][nt], frh, bil);
                    mma16(dI[mt][nt], frl, bih);
                }
            }
        }
    }

    if (mat != 2) {
        unsigned *QRh, *QRl, *QIh, *QIl;
        if (mat == 0) { QRh=g_krh; QRl=g_krl; QIh=g_kih; QIl=g_kil; }
        else          { QRh=g_qrh; QRl=g_qrl; QIh=g_qih; QIl=g_qil; }
        #pragma unroll
        for (int mt = 0; mt < 2; ++mt) {
            const int rA = m0 + wm*32 + mt*16 + g;
            const int rB = rA + 8;
            #pragma unroll
            for (int nt = 0; nt < 4; ++nt) {
                const int pidx = wn*16 + nt*4 + kl;
                float h0,l0,h1,l1;
                split1(dR[mt][nt][0],h0,l0); split1(dR[mt][nt][1],h1,l1);
                QRh[(size_t)rA*32 + pidx] = pkbf2(h0,h1);
                QRl[(size_t)rA*32 + pidx] = pkbf2(l0,l1);
                split1(dR[mt][nt][2],h0,l0); split1(dR[mt][nt][3],h1,l1);
                QRh[(size_t)rB*32 + pidx] = pkbf2(h0,h1);
                QRl[(size_t)rB*32 + pidx] = pkbf2(l0,l1);
                split1(dI[mt][nt][0],h0,l0); split1(dI[mt][nt][1],h1,l1);
                QIh[(size_t)rA*32 + pidx] = pkbf2(h0,h1);
                QIl[(size_t)rA*32 + pidx] = pkbf2(l0,l1);
                split1(dI[mt][nt][2],h0,l0); split1(dI[mt][nt][3],h1,l1);
                QIh[(size_t)rB*32 + pidx] = pkbf2(h0,h1);
                QIl[(size_t)rB*32 + pidx] = pkbf2(l0,l1);
            }
        }
    } else {
        #pragma unroll
        for (int mt = 0; mt < 2; ++mt) {
            const int rA = m0 + wm*32 + mt*16 + g;    // parity(rA) == parity(g)
            const int rB = rA + 8;
            #pragma unroll
            for (int nt = 0; nt < 4; ++nt) {
                const int c0 = wn*32 + nt*8 + 2*kl;
                float pr[4], pi[4];
                #pragma unroll
                for (int r=0;r<4;++r) {
                    pr[r] = __shfl_xor_sync(~0u, dR[mt][nt][r], 4);
                    pi[r] = __shfl_xor_sync(~0u, dI[mt][nt][r], 4);
                }
                if ((g & 1) == 0) {
                    const size_t pA = (size_t)(rA >> 1);
                    const size_t pB = (size_t)(rB >> 1);
                    float h0,l0,h1,l1;
                    split1(dR[mt][nt][0],h0,l0); split1(pr[0],h1,l1);
                    g_vrh[(size_t)c0*(M_/2) + pA] = pkbf2(h0,h1);
                    g_vrl[(size_t)c0*(M_/2) + pA] = pkbf2(l0,l1);
                    split1(dR[mt][nt][1],h0,l0); split1(pr[1],h1,l1);
                    g_vrh[(size_t)(c0+1)*(M_/2) + pA] = pkbf2(h0,h1);
                    g_vrl[(size_t)(c0+1)*(M_/2) + pA] = pkbf2(l0,l1);
                    split1(dR[mt][nt][2],h0,l0); split1(pr[2],h1,l1);
                    g_vrh[(size_t)c0*(M_/2) + pB] = pkbf2(h0,h1);
                    g_vrl[(size_t)c0*(M_/2) + pB] = pkbf2(l0,l1);
                    split1(dR[mt][nt][3],h0,l0); split1(pr[3],h1,l1);
                    g_vrh[(size_t)(c0+1)*(M_/2) + pB] = pkbf2(h0,h1);
                    g_vrl[(size_t)(c0+1)*(M_/2) + pB] = pkbf2(l0,l1);
                    split1(dI[mt][nt][0],h0,l0); split1(pi[0],h1,l1);
                    g_vih[(size_t)c0*(M_/2) + pA] = pkbf2(h0,h1);
                    g_vil[(size_t)c0*(M_/2) + pA] = pkbf2(l0,l1);
                    split1(dI[mt][nt][1],h0,l0); split1(pi[1],h1,l1);
                    g_vih[(size_t)(c0+1)*(M_/2) + pA] = pkbf2(h0,h1);
                    g_vil[(size_t)(c0+1)*(M_/2) + pA] = pkbf2(l0,l1);
                    split1(dI[mt][nt][2],h0,l0); split1(pi[2],h1,l1);
                    g_vih[(size_t)c0*(M_/2) + pB] = pkbf2(h0,h1);
                    g_vil[(size_t)c0*(M_/2) + pB] = pkbf2(l0,l1);
                    split1(dI[mt][nt][3],h0,l0); split1(pi[3],h1,l1);
                    g_vih[(size_t)(c0+1)*(M_/2) + pB] = pkbf2(h0,h1);
                    g_vil[(size_t)(c0+1)*(M_/2) + pB] = pkbf2(l0,l1);
                }
            }
        }
    }
}

// ===========================================================================
// Flash attention, causal-paired, NO online softmax (scores bounded -> plain
// exp, register row-sums, single final reduction). 3 syncs/step.
// ===========================================================================
#define AQH 0
#define AQL 4608
#define APH 9216
#define APL 11520
#define AKV 13824
#define KV_STAGE 18432
#define AT_U32 (13824 + 2*18432)
#define AT_BYTES ((AT_U32 + 256)*4)

__global__ __launch_bounds__(512, 1) void attn_kernel(float* __restrict__ out)
{
    extern __shared__ unsigned smu[];
    float* reds = (float*)(smu + AT_U32);   // [4][64]
    const unsigned sbase = smem_u32(smu);

    const int b    = blockIdx.y;
    const int pp   = blockIdx.x;           // pair id 0..15
    const int tid  = threadIdx.x;
    const int lane = tid & 31;
    const int w    = tid >> 5;
    const int wm   = w >> 2;
    const int wn   = w & 3;
    const int g    = lane >> 2;
    const int kl   = lane & 3;
    const int lr0 = wm*16 + g, lr1 = lr0 + 8;

    const int sm_row = tid >> 3;
    const int sm_qq  = (tid & 7)*4;

    #pragma unroll 1
    for (int pass = 0; pass < 2; ++pass) {
        const int qt = pass ? pp : (31 - pp);
        const int qbase = b*T_ + qt*64;

        {   // prologue: prefetch K/V tile 0 into stage 0
            const int kb_row = b*T_;
            const unsigned so = sbase + (unsigned)(AKV + sm_row*36 + sm_qq)*4u;
            const size_t kb = (size_t)(kb_row + sm_row)*32 + sm_qq;
            cpa16(so + 0*2304*4, &g_krh[kb]);
            cpa16(so + 1*2304*4, &g_kih[kb]);
            cpa16(so + 2*2304*4, &g_krl[kb]);
            cpa16(so + 3*2304*4, &g_kil[kb]);
            const size_t vb = (size_t)sm_row*(M_/2) + (size_t)(kb_row >> 1) + sm_qq;
            cpa16(so + 4*2304*4, &g_vrh[vb]);
            cpa16(so + 5*2304*4, &g_vih[vb]);
            cpa16(so + 6*2304*4, &g_vrl[vb]);
            cpa16(so + 7*2304*4, &g_vil[vb]);
            CP_COMMIT();
        }
        {   // stage Q
            const size_t base = (size_t)(qbase + sm_row)*32 + sm_qq;
            *(uint4*)&smu[AQH +        sm_row*36 + sm_qq] = *(const uint4*)&g_qrh[base];
            *(uint4*)&smu[AQH + 2304 + sm_row*36 + sm_qq] = *(const uint4*)&g_qih[base];
            *(uint4*)&smu[AQL +        sm_row*36 + sm_qq] = *(const uint4*)&g_qrl[base];
            *(uint4*)&smu[AQL + 2304 + sm_row*36 + sm_qq] = *(const uint4*)&g_qil[base];
        }

        float Or[2][4], Oi[2][4];
        float rs0 = 0.f, rs1 = 0.f;    // running row sums (this warp's columns)
        #pragma unroll
        for (int nt=0;nt<2;nt++)
            #pragma unroll
            for (int r=0;r<4;r++) { Or[nt][r]=0.f; Oi[nt][r]=0.f; }

        for (int kt = 0; kt <= qt; ++kt) {
            const int cur = kt & 1;
            __syncthreads();   // prior PV reads of stage 1-cur & Ps done
            if (kt < qt) {
                const int kb_row = b*T_ + (kt+1)*64;
                const unsigned so = sbase
                    + (unsigned)(AKV + (1-cur)*KV_STAGE + sm_row*36 + sm_qq)*4u;
                const size_t kb = (size_t)(kb_row + sm_row)*32 + sm_qq;
                cpa16(so + 0*2304*4, &g_krh[kb]);
                cpa16(so + 1*2304*4, &g_kih[kb]);
                cpa16(so + 2*2304*4, &g_krl[kb]);
                cpa16(so + 3*2304*4, &g_kil[kb]);
                const size_t vb = (size_t)sm_row*(M_/2) + (size_t)(kb_row >> 1) + sm_qq;
                cpa16(so + 4*2304*4, &g_vrh[vb]);
                cpa16(so + 5*2304*4, &g_vih[vb]);
                cpa16(so + 6*2304*4, &g_vrl[vb]);
                cpa16(so + 7*2304*4, &g_vil[vb]);
                CP_COMMIT();
                CP_WAIT1();
            } else {
                CP_WAIT0();
            }
            __syncthreads();   // current stage visible

            const int KH = AKV + cur*KV_STAGE;
            const int KL = KH + 4608;
            const int VH = KH + 9216;
            const int VL = KH + 13824;

            // ---- scores ----
            float Sr[2][4], Si[2][4];
            #pragma unroll
            for (int nt=0;nt<2;nt++)
                #pragma unroll
                for (int r=0;r<4;r++) { Sr[nt][r]=0.f; Si[nt][r]=0.f; }

            #pragma unroll
            for (int ks = 0; ks < 4; ++ks) {
                const int pb = ks*8;
                const int m = wm*16 + g;
                unsigned qrh[4], qrl[4], qih[4], qil[4];
                #pragma unroll
                for (int q = 0; q < 4; ++q) {
                    const int rr = m + ((q & 1) ? 8 : 0);
                    const int cc = pb + kl + ((q >> 1) ? 4 : 0);
                    qrh[q]=smu[AQH +        rr*36 + cc];
                    qrl[q]=smu[AQL +        rr*36 + cc];
                    qih[q]=smu[AQH + 2304 + rr*36 + cc];
                    qil[q]=smu[AQL + 2304 + rr*36 + cc];
                }
                #pragma unroll
                for (int nt = 0; nt < 2; ++nt) {
                    const int n0 = wn*16 + nt*8 + g;
                    unsigned krh[2], krl[2], kih[2], kil[2], nih[2], nil_[2];
                    krh[0]=smu[KH +        n0*36 + pb+kl];
                    krh[1]=smu[KH +        n0*36 + pb+kl+4];
                    krl[0]=smu[KL +        n0*36 + pb+kl];
                    krl[1]=smu[KL +        n0*36 + pb+kl+4];
                    kih[0]=smu[KH + 2304 + n0*36 + pb+kl];
                    kih[1]=smu[KH + 2304 + n0*36 + pb+kl+4];
                    kil[0]=smu[KL + 2304 + n0*36 + pb+kl];
                    kil[1]=smu[KL + 2304 + n0*36 + pb+kl+4];
                    nih[0]=kih[0]^0x80008000u; nih[1]=kih[1]^0x80008000u;
                    nil_[0]=kil[0]^0x80008000u; nil_[1]=kil[1]^0x80008000u;
                    mma16(Sr[nt], qrh, krh);
                    mma16(Sr[nt], qrh, krl);
                    mma16(Sr[nt], qrl, krh);
                    mma16(Sr[nt], qih, kih);
                    mma16(Sr[nt], qih, kil);
                    mma16(Sr[nt], qil, kih);
                    mma16(Si[nt], qih, krh);
                    mma16(Si[nt], qih, krl);
                    mma16(Si[nt], qil, krh);
                    mma16(Si[nt], qrh, nih);
                    mma16(Si[nt], qrh, nil_);
                    mma16(Si[nt], qrl, nih);
                }
            }

            // ---- magnitude + mask + plain exp + P store ----
            #pragma unroll
            for (int nt = 0; nt < 2; ++nt) {
                float e[4];
                #pragma unroll
                for (int r = 0; r < 4; ++r) {
                    const float sr = Sr[nt][r], si = Si[nt][r];
                    const float m2 = fmaf(sr, sr, fmaf(si, si, 1e-4f));
                    const float v = m2 * rsqrtf(m2) * 0.125f;
                    const int colg = kt*64 + wn*16 + nt*8 + 2*kl + (r&1);
                    const int rowg = qt*64 + ((r<2) ? lr0 : lr1);
                    e[r] = (colg <= rowg) ? __expf(v) : 0.f;
                }
                rs0 += e[0] + e[1];
                rs1 += e[2] + e[3];
                const int pidx = wn*8 + nt*4 + kl;
                float h0,l0,h1,l1,h2,l2,h3,l3;
                split1(e[0],h0,l0); split1(e[1],h1,l1);
                split1(e[2],h2,l2); split1(e[3],h3,l3);
                smu[APH + lr0*36 + pidx] = pkbf2(h0,h1);
                smu[APL + lr0*36 + pidx] = pkbf2(l0,l1);
                smu[APH + lr1*36 + pidx] = pkbf2(h2,h3);
                smu[APL + lr1*36 + pidx] = pkbf2(l2,l3);
            }
            __syncthreads();   // Ps visible to all warps

            // ---- O += P @ V ----
            #pragma unroll
            for (int ks = 0; ks < 4; ++ks) {
                const int pb = ks*8;
                const int m = wm*16 + g;
                unsigned aph[4], apl[4];
                #pragma unroll
                for (int q = 0; q < 4; ++q) {
                    const int rr = m + ((q & 1) ? 8 : 0);
                    const int cc = pb + kl + ((q >> 1) ? 4 : 0);
                    aph[q]=smu[APH + rr*36 + cc];
                    apl[q]=smu[APL + rr*36 + cc];
                }
                #pragma unroll
                for (int nt = 0; nt < 2; ++nt) {
                    const int n0 = wn*16 + nt*8 + g;
                    unsigned bvh[2], bvl[2], bwh[2], bwl[2];
                    bvh[0]=smu[VH +        n0*36 + pb+kl];
                    bvh[1]=smu[VH +        n0*36 + pb+kl+4];
                    bvl[0]=smu[VL +        n0*36 + pb+kl];
                    bvl[1]=smu[VL +        n0*36 + pb+kl+4];
                    bwh[0]=smu[VH + 2304 + n0*36 + pb+kl];
                    bwh[1]=smu[VH + 2304 + n0*36 + pb+kl+4];
                    bwl[0]=smu[VL + 2304 + n0*36 + pb+kl];
                    bwl[1]=smu[VL + 2304 + n0*36 + pb+kl+4];
                    mma16(Or[nt], aph, bvh);
                    mma16(Or[nt], aph, bvl);
                    mma16(Or[nt], apl, bvh);
                    mma16(Oi[nt], aph, bwh);
                    mma16(Oi[nt], aph, bwl);
                    mma16(Oi[nt], apl, bwh);
                }
            }
        }

        // ---- final row-sum reduction across quad lanes + 4 wn warps ----
        rs0 += __shfl_xor_sync(~0u, rs0, 1);
        rs0 += __shfl_xor_sync(~0u, rs0, 2);
        rs1 += __shfl_xor_sync(~0u, rs1, 1);
        rs1 += __shfl_xor_sync(~0u, rs1, 2);
        __syncthreads();   // Ps reads of last step done before reds reuse? (reds is separate; protects pass-2 ordering)
        if (kl == 0) { reds[wn*64 + lr0] = rs0; reds[wn*64 + lr1] = rs1; }
        __syncthreads();

        const float inv0 = 1.f / (reds[lr0] + reds[64+lr0] + reds[128+lr0] + reds[192+lr0]);
        const float inv1 = 1.f / (reds[lr1] + reds[64+lr1] + reds[128+lr1] + reds[192+lr1]);
        #pragma unroll
        for (int nt = 0; nt < 2; ++nt) {
            const int h0 = wn*16 + nt*8 + 2*kl;
            const size_t rA = (size_t)(qbase + lr0);
            const size_t rB = (size_t)(qbase + lr1);
            *(float2*)(out + rA*H_ + h0) = make_float2(Or[nt][0]*inv0, Or[nt][1]*inv0);
            *(float2*)(out + rB*H_ + h0) = make_float2(Or[nt][2]*inv1, Or[nt][3]*inv1);
            *(float2*)(out + (size_t)M_*H_ + rA*H_ + h0) = make_float2(Oi[nt][0]*inv0, Oi[nt][1]*inv0);
            *(float2*)(out + (size_t)M_*H_ + rB*H_ + h0) = make_float2(Oi[nt][2]*inv1, Oi[nt][3]*inv1);
        }
        __syncthreads();   // reds/stage reads done before next pass restarts
    }
}

// ---------------------------------------------------------------------------
extern "C" void kernel_launch(void* const* d_in, const int* in_sizes, int n_in,
                              void* d_out, int out_size)
{
    const float* xr  = (const float*)d_in[0];
    const float* xi  = (const float*)d_in[1];
    const float* Wkr = (const float*)d_in[2];
    const float* Wki = (const float*)d_in[3];
    const float* Wqr = (const float*)d_in[4];
    const float* Wqi = (const float*)d_in[5];
    const float* Wvr = (const float*)d_in[6];
    const float* Wvi = (const float*)d_in[7];

    cudaFuncSetAttribute(proj_kernel,
        cudaFuncAttributeMaxDynamicSharedMemorySize, PJ_U32*4);
    cudaFuncSetAttribute(attn_kernel,
        cudaFuncAttributeMaxDynamicSharedMemorySize, AT_BYTES);

    proj_kernel<<<(M_/128)*3, 256, PJ_U32*4>>>(xr, xi, Wkr, Wki, Wqr, Wqi, Wvr, Wvi);

    dim3 ag(T_/128, B_);   // 16 pairs x 8 batches
    attn_kernel<<<ag, 512, AT_BYTES>>>((float*)d_out);
}

// round 15
// speedup vs baseline: 1.0395x; 1.0395x over previous
#include <cuda_runtime.h>
#include <cuda_bf16.h>
#include <math_constants.h>

#define B_ 8
#define T_ 2048
#define C_ 1024
#define H_ 64
#define M_ (B_*T_)

// Packed bf16 hi/lo pairs (u32 = two bf16 along the mma k-dim).
// Q,K: [M][32] pairs along h.  V: transposed [H][M/2] pairs along key index.
__device__ unsigned g_qrh[M_*32], g_qrl[M_*32], g_qih[M_*32], g_qil[M_*32];
__device__ unsigned g_krh[M_*32], g_krl[M_*32], g_kih[M_*32], g_kil[M_*32];
__device__ unsigned g_vrh[(size_t)H_*(M_/2)], g_vrl[(size_t)H_*(M_/2)];
__device__ unsigned g_vih[(size_t)H_*(M_/2)], g_vil[(size_t)H_*(M_/2)];

__device__ __forceinline__ unsigned pkbf2(float lo, float hi) {
    unsigned r; asm("cvt.rn.bf16x2.f32 %0, %1, %2;" : "=r"(r) : "f"(hi), "f"(lo));
    return r;
}
__device__ __forceinline__ void split1(float x, float& h, float& l) {
    h = __bfloat162float(__float2bfloat16(x));
    l = x - h;
}
__device__ __forceinline__ void mma16(float* d, const unsigned* a, const unsigned* b) {
    asm volatile("mma.sync.aligned.m16n8k16.row.col.f32.bf16.bf16.f32 "
        "{%0,%1,%2,%3}, {%4,%5,%6,%7}, {%8,%9}, {%0,%1,%2,%3};"
        : "+f"(d[0]), "+f"(d[1]), "+f"(d[2]), "+f"(d[3])
        : "r"(a[0]), "r"(a[1]), "r"(a[2]), "r"(a[3]), "r"(b[0]), "r"(b[1]));
}
__device__ __forceinline__ unsigned smem_u32(const void* p) {
    unsigned a;
    asm("{ .reg .u64 t; cvta.to.shared.u64 t, %1; cvt.u32.u64 %0, t; }"
        : "=r"(a) : "l"(p));
    return a;
}
__device__ __forceinline__ void cpa16(unsigned saddr, const void* g) {
    asm volatile("cp.async.cg.shared.global [%0], [%1], 16;"
                 :: "r"(saddr), "l"(g) : "memory");
}
__device__ __forceinline__ void ldsm4(unsigned* r, unsigned addr) {
    asm volatile("ldmatrix.sync.aligned.m8n8.x4.shared.b16 {%0,%1,%2,%3}, [%4];"
        : "=r"(r[0]), "=r"(r[1]), "=r"(r[2]), "=r"(r[3]) : "r"(addr));
}
#define CP_COMMIT() asm volatile("cp.async.commit_group;" ::: "memory")
#define CP_WAIT1()  asm volatile("cp.async.wait_group 1;" ::: "memory")
#define CP_WAIT0()  asm volatile("cp.async.wait_group 0;" ::: "memory")

// ===========================================================================
// Projection (unchanged): bf16-split HMMA, scalar split staging.
// ===========================================================================
#define PJ_AB0 0
#define PJ_BB0 10240
#define PJ_U32 15360

__global__ __launch_bounds__(256, 2) void proj_kernel(
    const float* __restrict__ xr,  const float* __restrict__ xi,
    const float* __restrict__ Wkr, const float* __restrict__ Wki,
    const float* __restrict__ Wqr, const float* __restrict__ Wqi,
    const float* __restrict__ Wvr, const float* __restrict__ Wvi)
{
    extern __shared__ unsigned smu[];
    unsigned* As = smu + PJ_AB0;
    unsigned* Bs = smu + PJ_BB0;

    const int tid  = threadIdx.x;
    const int lane = tid & 31;
    const int w    = tid >> 5;
    const int wm   = w >> 1;
    const int wn   = w & 1;
    const int g    = lane >> 2;
    const int kl   = lane & 3;

    const int rt  = blockIdx.x / 3;
    const int mat = blockIdx.x % 3;
    const int m0  = rt * 128;

    const float* Wr_ = (mat==0)? Wkr : (mat==1)? Wqr : Wvr;
    const float* Wi_ = (mat==0)? Wki : (mat==1)? Wqi : Wvi;

    float dR[2][4][4], dI[2][4][4];
    #pragma unroll
    for (int mt=0; mt<2; ++mt)
        #pragma unroll
        for (int nt=0; nt<4; ++nt)
            #pragma unroll
            for (int r=0; r<4; ++r) { dR[mt][nt][r]=0.f; dI[mt][nt][r]=0.f; }

    const int a_ri = tid >> 7;
    const int a_m  = tid & 127;
    const float* a_src = (a_ri ? xi : xr) + (size_t)(m0 + a_m)*C_;
    unsigned* a_h = As + (a_ri*2    )*2560 + a_m*20;
    unsigned* a_l = As + (a_ri*2 + 1)*2560 + a_m*20;
    const int b_n  = tid & 63;
    const int b_kq = tid >> 6;

    for (int c0 = 0; c0 < C_; c0 += 32) {
        __syncthreads();
        #pragma unroll
        for (int j = 0; j < 8; ++j) {
            float4 v = *(const float4*)(a_src + c0 + j*4);
            float h0,l0,h1,l1,h2,l2,h3,l3;
            split1(v.x,h0,l0); split1(v.y,h1,l1);
            split1(v.z,h2,l2); split1(v.w,h3,l3);
            a_h[j*2  ] = pkbf2(h0,h1);
            a_h[j*2+1] = pkbf2(h2,h3);
            a_l[j*2  ] = pkbf2(l0,l1);
            a_l[j*2+1] = pkbf2(l2,l3);
        }
        #pragma unroll
        for (int jj = 0; jj < 4; ++jj) {
            const int k2 = jj*4 + b_kq;
            const size_t krow = (size_t)(c0 + 2*k2);
            float wr0 = Wr_[krow*H_ + b_n], wr1 = Wr_[(krow+1)*H_ + b_n];
            float wi0 = Wi_[krow*H_ + b_n], wi1 = Wi_[(krow+1)*H_ + b_n];
            float h0,l0,h1,l1,h2,l2,h3,l3;
            split1(wr0,h0,l0); split1(wr1,h1,l1);
            split1(wi0,h2,l2); split1(wi1,h3,l3);
            Bs[0*1280 + b_n*20 + k2] = pkbf2(h0,h1);
            Bs[1*1280 + b_n*20 + k2] = pkbf2(l0,l1);
            Bs[2*1280 + b_n*20 + k2] = pkbf2(h2,h3);
            Bs[3*1280 + b_n*20 + k2] = pkbf2(l2,l3);
        }
        __syncthreads();

        #pragma unroll
        for (int ks = 0; ks < 2; ++ks) {
            const int pb = ks*8;
            #pragma unroll
            for (int mt = 0; mt < 2; ++mt) {
                const int mrow = wm*32 + mt*16 + g;
                unsigned frh[4], frl[4], fih[4], fil[4];
                #pragma unroll
                for (int q = 0; q < 4; ++q) {
                    const int rr = mrow + ((q & 1) ? 8 : 0);
                    const int cc = pb + kl + ((q >> 1) ? 4 : 0);
                    frh[q] = As[0*2560 + rr*20 + cc];
                    frl[q] = As[1*2560 + rr*20 + cc];
                    fih[q] = As[2*2560 + rr*20 + cc];
                    fil[q] = As[3*2560 + rr*20 + cc];
                }
                #pragma unroll
                for (int nt = 0; nt < 4; ++nt) {
                    const int n0 = wn*32 + nt*8 + g;
                    unsigned brh[2], brl[2], bih[2], bil[2], nih[2], nil_[2];
                    brh[0]=Bs[0*1280 + n0*20 + pb+kl];
                    brh[1]=Bs[0*1280 + n0*20 + pb+kl+4];
                    brl[0]=Bs[1*1280 + n0*20 + pb+kl];
                    brl[1]=Bs[1*1280 + n0*20 + pb+kl+4];
                    bih[0]=Bs[2*1280 + n0*20 + pb+kl];
                    bih[1]=Bs[2*1280 + n0*20 + pb+kl+4];
                    bil[0]=Bs[3*1280 + n0*20 + pb+kl];
                    bil[1]=Bs[3*1280 + n0*20 + pb+kl+4];
                    nih[0]=bih[0]^0x80008000u; nih[1]=bih[1]^0x80008000u;
                    nil_[0]=bil[0]^0x80008000u; nil_[1]=bil[1]^0x80008000u;
                    mma16(dR[mt][nt], frh, brh);
                    mma16(dR[mt][nt], frh, brl);
                    mma16(dR[mt][nt], frl, brh);
                    mma16(dR[mt][nt], fih, nih);
                    mma16(dR[mt][nt], fih, nil_);
                    mma16(dR[mt][nt], fil, nih);
                    mma16(dI[mt][nt], fih, brh);
                    mma16(dI[mt][nt], fih, brl);
                    mma16(dI[mt][nt], fil, brh);
                    mma16(dI[mt][nt], frh, bih);
                    mma16(dI[mt][nt], frh, bil);
                    mma16(dI[mt][nt], frl, bih);
                }
            }
        }
    }

    if (mat != 2) {
        unsigned *QRh, *QRl, *QIh, *QIl;
        if (mat == 0) { QRh=g_krh; QRl=g_krl; QIh=g_kih; QIl=g_kil; }
        else          { QRh=g_qrh; QRl=g_qrl; QIh=g_qih; QIl=g_qil; }
        #pragma unroll
        for (int mt = 0; mt < 2; ++mt) {
            const int rA = m0 + wm*32 + mt*16 + g;
            const int rB = rA + 8;
            #pragma unroll
            for (int nt = 0; nt < 4; ++nt) {
                const int pidx = wn*16 + nt*4 + kl;
                float h0,l0,h1,l1;
                split1(dR[mt][nt][0],h0,l0); split1(dR[mt][nt][1],h1,l1);
                QRh[(size_t)rA*32 + pidx] = pkbf2(h0,h1);
                QRl[(size_t)rA*32 + pidx] = pkbf2(l0,l1);
                split1(dR[mt][nt][2],h0,l0); split1(dR[mt][nt][3],h1,l1);
                QRh[(size_t)rB*32 + pidx] = pkbf2(h0,h1);
                QRl[(size_t)rB*32 + pidx] = pkbf2(l0,l1);
                split1(dI[mt][nt][0],h0,l0); split1(dI[mt][nt][1],h1,l1);
                QIh[(size_t)rA*32 + pidx] = pkbf2(h0,h1);
                QIl[(size_t)rA*32 + pidx] = pkbf2(l0,l1);
                split1(dI[mt][nt][2],h0,l0); split1(dI[mt][nt][3],h1,l1);
                QIh[(size_t)rB*32 + pidx] = pkbf2(h0,h1);
                QIl[(size_t)rB*32 + pidx] = pkbf2(l0,l1);
            }
        }
    } else {
        #pragma unroll
        for (int mt = 0; mt < 2; ++mt) {
            const int rA = m0 + wm*32 + mt*16 + g;    // parity(rA) == parity(g)
            const int rB = rA + 8;
            #pragma unroll
            for (int nt = 0; nt < 4; ++nt) {
                const int c0 = wn*32 + nt*8 + 2*kl;
                float pr[4], pi[4];
                #pragma unroll
                for (int r=0;r<4;++r) {
                    pr[r] = __shfl_xor_sync(~0u, dR[mt][nt][r], 4);
                    pi[r] = __shfl_xor_sync(~0u, dI[mt][nt][r], 4);
                }
                if ((g & 1) == 0) {
                    const size_t pA = (size_t)(rA >> 1);
                    const size_t pB = (size_t)(rB >> 1);
                    float h0,l0,h1,l1;
                    split1(dR[mt][nt][0],h0,l0); split1(pr[0],h1,l1);
                    g_vrh[(size_t)c0*(M_/2) + pA] = pkbf2(h0,h1);
                    g_vrl[(size_t)c0*(M_/2) + pA] = pkbf2(l0,l1);
                    split1(dR[mt][nt][1],h0,l0); split1(pr[1],h1,l1);
                    g_vrh[(size_t)(c0+1)*(M_/2) + pA] = pkbf2(h0,h1);
                    g_vrl[(size_t)(c0+1)*(M_/2) + pA] = pkbf2(l0,l1);
                    split1(dR[mt][nt][2],h0,l0); split1(pr[2],h1,l1);
                    g_vrh[(size_t)c0*(M_/2) + pB] = pkbf2(h0,h1);
                    g_vrl[(size_t)c0*(M_/2) + pB] = pkbf2(l0,l1);
                    split1(dR[mt][nt][3],h0,l0); split1(pr[3],h1,l1);
                    g_vrh[(size_t)(c0+1)*(M_/2) + pB] = pkbf2(h0,h1);
                    g_vrl[(size_t)(c0+1)*(M_/2) + pB] = pkbf2(l0,l1);
                    split1(dI[mt][nt][0],h0,l0); split1(pi[0],h1,l1);
                    g_vih[(size_t)c0*(M_/2) + pA] = pkbf2(h0,h1);
                    g_vil[(size_t)c0*(M_/2) + pA] = pkbf2(l0,l1);
                    split1(dI[mt][nt][1],h0,l0); split1(pi[1],h1,l1);
                    g_vih[(size_t)(c0+1)*(M_/2) + pA] = pkbf2(h0,h1);
                    g_vil[(size_t)(c0+1)*(M_/2) + pA] = pkbf2(l0,l1);
                    split1(dI[mt][nt][2],h0,l0); split1(pi[2],h1,l1);
                    g_vih[(size_t)c0*(M_/2) + pB] = pkbf2(h0,h1);
                    g_vil[(size_t)c0*(M_/2) + pB] = pkbf2(l0,l1);
                    split1(dI[mt][nt][3],h0,l0); split1(pi[3],h1,l1);
                    g_vih[(size_t)(c0+1)*(M_/2) + pB] = pkbf2(h0,h1);
                    g_vil[(size_t)(c0+1)*(M_/2) + pB] = pkbf2(l0,l1);
                }
            }
        }
    }
}

// ===========================================================================
// Flash attention, causal-paired, plain-exp softmax, ldmatrix fragment loads.
// ===========================================================================
#define AQH 0
#define AQL 4608
#define APH 9216
#define APL 11520
#define AKV 13824
#define KV_STAGE 18432
#define AT_U32 (13824 + 2*18432)
#define AT_BYTES ((AT_U32 + 256)*4)

__global__ __launch_bounds__(512, 1) void attn_kernel(float* __restrict__ out)
{
    extern __shared__ unsigned smu[];
    float* reds = (float*)(smu + AT_U32);   // [4][64]
    const unsigned sbase = smem_u32(smu);

    const int b    = blockIdx.y;
    const int pp   = blockIdx.x;           // pair id 0..15
    const int tid  = threadIdx.x;
    const int lane = tid & 31;
    const int w    = tid >> 5;
    const int wm   = w >> 2;
    const int wn   = w & 3;
    const int g    = lane >> 2;
    const int kl   = lane & 3;
    const int lr0 = wm*16 + g, lr1 = lr0 + 8;

    const int sm_row = tid >> 3;
    const int sm_qq  = (tid & 7)*4;

    // ldmatrix per-lane address components (u32 units):
    // A-type (Q/P, 16 rows x 8 pairs): tiles = (row half, pair half)
    const unsigned a_off = (unsigned)((wm*16 + (((lane>>3)&1)<<3) + (lane&7))*36
                                      + ((lane>>4)<<2));
    // B-type (K/V, 8 rows x 8 pairs, hi/lo arrays 4608 apart):
    const unsigned b_off = (unsigned)(((lane>>4) ? 4608 : 0)
                                      + (lane&7)*36 + (((lane>>3)&1)<<2));

    #pragma unroll 1
    for (int pass = 0; pass < 2; ++pass) {
        const int qt = pass ? pp : (31 - pp);
        const int qbase = b*T_ + qt*64;

        {   // prologue: prefetch K/V tile 0 into stage 0
            const int kb_row = b*T_;
            const unsigned so = sbase + (unsigned)(AKV + sm_row*36 + sm_qq)*4u;
            const size_t kb = (size_t)(kb_row + sm_row)*32 + sm_qq;
            cpa16(so + 0*2304*4, &g_krh[kb]);
            cpa16(so + 1*2304*4, &g_kih[kb]);
            cpa16(so + 2*2304*4, &g_krl[kb]);
            cpa16(so + 3*2304*4, &g_kil[kb]);
            const size_t vb = (size_t)sm_row*(M_/2) + (size_t)(kb_row >> 1) + sm_qq;
            cpa16(so + 4*2304*4, &g_vrh[vb]);
            cpa16(so + 5*2304*4, &g_vih[vb]);
            cpa16(so + 6*2304*4, &g_vrl[vb]);
            cpa16(so + 7*2304*4, &g_vil[vb]);
            CP_COMMIT();
        }
        {   // stage Q
            const size_t base = (size_t)(qbase + sm_row)*32 + sm_qq;
            *(uint4*)&smu[AQH +        sm_row*36 + sm_qq] = *(const uint4*)&g_qrh[base];
            *(uint4*)&smu[AQH + 2304 + sm_row*36 + sm_qq] = *(const uint4*)&g_qih[base];
            *(uint4*)&smu[AQL +        sm_row*36 + sm_qq] = *(const uint4*)&g_qrl[base];
            *(uint4*)&smu[AQL + 2304 + sm_row*36 + sm_qq] = *(const uint4*)&g_qil[base];
        }

        float Or[2][4], Oi[2][4];
        float rs0 = 0.f, rs1 = 0.f;
        #pragma unroll
        for (int nt=0;nt<2;nt++)
            #pragma unroll
            for (int r=0;r<4;r++) { Or[nt][r]=0.f; Oi[nt][r]=0.f; }

        for (int kt = 0; kt <= qt; ++kt) {
            const int cur = kt & 1;
            __syncthreads();
            if (kt < qt) {
                const int kb_row = b*T_ + (kt+1)*64;
                const unsigned so = sbase
                    + (unsigned)(AKV + (1-cur)*KV_STAGE + sm_row*36 + sm_qq)*4u;
                const size_t kb = (size_t)(kb_row + sm_row)*32 + sm_qq;
                cpa16(so + 0*2304*4, &g_krh[kb]);
                cpa16(so + 1*2304*4, &g_kih[kb]);
                cpa16(so + 2*2304*4, &g_krl[kb]);
                cpa16(so + 3*2304*4, &g_kil[kb]);
                const size_t vb = (size_t)sm_row*(M_/2) + (size_t)(kb_row >> 1) + sm_qq;
                cpa16(so + 4*2304*4, &g_vrh[vb]);
                cpa16(so + 5*2304*4, &g_vih[vb]);
                cpa16(so + 6*2304*4, &g_vrl[vb]);
                cpa16(so + 7*2304*4, &g_vil[vb]);
                CP_COMMIT();
                CP_WAIT1();
            } else {
                CP_WAIT0();
            }
            __syncthreads();

            const unsigned KH = AKV + cur*KV_STAGE;        // + b_off covers KL
            const unsigned VH = KH + 9216;

            // ---- scores ----
            float Sr[2][4], Si[2][4];
            #pragma unroll
            for (int nt=0;nt<2;nt++)
                #pragma unroll
                for (int r=0;r<4;r++) { Sr[nt][r]=0.f; Si[nt][r]=0.f; }

            #pragma unroll
            for (int ks = 0; ks < 4; ++ks) {
                const unsigned pb = ks*8;
                unsigned qr_[4], ql_[4], qi_[4], qj_[4];   // qr hi, qr lo, qi hi, qi lo
                ldsm4(qr_, sbase + (AQH +        a_off + pb)*4u);
                ldsm4(ql_, sbase + (AQL +        a_off + pb)*4u);
                ldsm4(qi_, sbase + (AQH + 2304 + a_off + pb)*4u);
                ldsm4(qj_, sbase + (AQL + 2304 + a_off + pb)*4u);
                #pragma unroll
                for (int nt = 0; nt < 2; ++nt) {
                    const unsigned n0b = (unsigned)((wn*16 + nt*8)*36);
                    unsigned kr_[4], ki_[4], ni_[4];
                    ldsm4(kr_, sbase + (KH +        n0b + b_off + pb)*4u);
                    ldsm4(ki_, sbase + (KH + 2304 + n0b + b_off + pb)*4u);
                    // kr_ = {krh0,krh1,krl0,krl1}; ki_ likewise for imag
                    #pragma unroll
                    for (int r=0;r<4;++r) ni_[r] = ki_[r] ^ 0x80008000u;
                    mma16(Sr[nt], qr_, kr_);        // qrh x krh0/1
                    mma16(Sr[nt], qr_, kr_+2);      // qrh x krl
                    mma16(Sr[nt], ql_, kr_);        // qrl x krh
                    mma16(Sr[nt], qi_, ki_);
                    mma16(Sr[nt], qi_, ki_+2);
                    mma16(Sr[nt], qj_, ki_);
                    mma16(Si[nt], qi_, kr_);
                    mma16(Si[nt], qi_, kr_+2);
                    mma16(Si[nt], qj_, kr_);
                    mma16(Si[nt], qr_, ni_);
                    mma16(Si[nt], qr_, ni_+2);
                    mma16(Si[nt], ql_, ni_);
                }
            }

            // ---- magnitude + mask + plain exp + P store ----
            #pragma unroll
            for (int nt = 0; nt < 2; ++nt) {
                float e[4];
                #pragma unroll
                for (int r = 0; r < 4; ++r) {
                    const float sr = Sr[nt][r], si = Si[nt][r];
                    const float m2 = fmaf(sr, sr, fmaf(si, si, 1e-4f));
                    const float v = m2 * rsqrtf(m2) * 0.125f;
                    const int colg = kt*64 + wn*16 + nt*8 + 2*kl + (r&1);
                    const int rowg = qt*64 + ((r<2) ? lr0 : lr1);
                    e[r] = (colg <= rowg) ? __expf(v) : 0.f;
                }
                rs0 += e[0] + e[1];
                rs1 += e[2] + e[3];
                const int pidx = wn*8 + nt*4 + kl;
                float h0,l0,h1,l1,h2,l2,h3,l3;
                split1(e[0],h0,l0); split1(e[1],h1,l1);
                split1(e[2],h2,l2); split1(e[3],h3,l3);
                smu[APH + lr0*36 + pidx] = pkbf2(h0,h1);
                smu[APL + lr0*36 + pidx] = pkbf2(l0,l1);
                smu[APH + lr1*36 + pidx] = pkbf2(h2,h3);
                smu[APL + lr1*36 + pidx] = pkbf2(l2,l3);
            }
            __syncthreads();

            // ---- O += P @ V ----
            #pragma unroll
            for (int ks = 0; ks < 4; ++ks) {
                const unsigned pb = ks*8;
                unsigned ph_[4], pl_[4];
                ldsm4(ph_, sbase + (APH + a_off + pb)*4u);
                ldsm4(pl_, sbase + (APL + a_off + pb)*4u);
                #pragma unroll
                for (int nt = 0; nt < 2; ++nt) {
                    const unsigned n0b = (unsigned)((wn*16 + nt*8)*36);
                    unsigned vr_[4], vi_[4];
                    ldsm4(vr_, sbase + (VH +        n0b + b_off + pb)*4u);
                    ldsm4(vi_, sbase + (VH + 2304 + n0b + b_off + pb)*4u);
                    mma16(Or[nt], ph_, vr_);
                    mma16(Or[nt], ph_, vr_+2);
                    mma16(Or[nt], pl_, vr_);
                    mma16(Oi[nt], ph_, vi_);
                    mma16(Oi[nt], ph_, vi_+2);
                    mma16(Oi[nt], pl_, vi_);
                }
            }
        }

        // ---- final row-sum reduction ----
        rs0 += __shfl_xor_sync(~0u, rs0, 1);
        rs0 += __shfl_xor_sync(~0u, rs0, 2);
        rs1 += __shfl_xor_sync(~0u, rs1, 1);
        rs1 += __shfl_xor_sync(~0u, rs1, 2);
        __syncthreads();
        if (kl == 0) { reds[wn*64 + lr0] = rs0; reds[wn*64 + lr1] = rs1; }
        __syncthreads();

        const float inv0 = 1.f / (reds[lr0] + reds[64+lr0] + reds[128+lr0] + reds[192+lr0]);
        const float inv1 = 1.f / (reds[lr1] + reds[64+lr1] + reds[128+lr1] + reds[192+lr1]);
        #pragma unroll
        for (int nt = 0; nt < 2; ++nt) {
            const int h0 = wn*16 + nt*8 + 2*kl;
            const size_t rA = (size_t)(qbase + lr0);
            const size_t rB = (size_t)(qbase + lr1);
            *(float2*)(out + rA*H_ + h0) = make_float2(Or[nt][0]*inv0, Or[nt][1]*inv0);
            *(float2*)(out + rB*H_ + h0) = make_float2(Or[nt][2]*inv1, Or[nt][3]*inv1);
            *(float2*)(out + (size_t)M_*H_ + rA*H_ + h0) = make_float2(Oi[nt][0]*inv0, Oi[nt][1]*inv0);
            *(float2*)(out + (size_t)M_*H_ + rB*H_ + h0) = make_float2(Oi[nt][2]*inv1, Oi[nt][3]*inv1);
        }
        __syncthreads();
    }
}

// ---------------------------------------------------------------------------
extern "C" void kernel_launch(void* const* d_in, const int* in_sizes, int n_in,
                              void* d_out, int out_size)
{
    const float* xr  = (const float*)d_in[0];
    const float* xi  = (const float*)d_in[1];
    const float* Wkr = (const float*)d_in[2];
    const float* Wki = (const float*)d_in[3];
    const float* Wqr = (const float*)d_in[4];
    const float* Wqi = (const float*)d_in[5];
    const float* Wvr = (const float*)d_in[6];
    const float* Wvi = (const float*)d_in[7];

    cudaFuncSetAttribute(proj_kernel,
        cudaFuncAttributeMaxDynamicSharedMemorySize, PJ_U32*4);
    cudaFuncSetAttribute(attn_kernel,
        cudaFuncAttributeMaxDynamicSharedMemorySize, AT_BYTES);

    proj_kernel<<<(M_/128)*3, 256, PJ_U32*4>>>(xr, xi, Wkr, Wki, Wqr, Wqi, Wvr, Wvi);

    dim3 ag(T_/128, B_);   // 16 pairs x 8 batches
    attn_kernel<<<ag, 512, AT_BYTES>>>((float*)d_out);
}

// round 16
// speedup vs baseline: 1.0835x; 1.0423x over previous
#include <cuda_runtime.h>
#include <cuda_bf16.h>
#include <math_constants.h>

#define B_ 8
#define T_ 2048
#define C_ 1024
#define H_ 64
#define M_ (B_*T_)

// Packed bf16 hi/lo pairs (u32 = two bf16 along the mma k-dim).
__device__ unsigned g_qrh[M_*32], g_qrl[M_*32], g_qih[M_*32], g_qil[M_*32];
__device__ unsigned g_krh[M_*32], g_krl[M_*32], g_kih[M_*32], g_kil[M_*32];
__device__ unsigned g_vrh[(size_t)H_*(M_/2)], g_vrl[(size_t)H_*(M_/2)];
__device__ unsigned g_vih[(size_t)H_*(M_/2)], g_vil[(size_t)H_*(M_/2)];

__device__ __forceinline__ unsigned pkbf2(float lo, float hi) {
    unsigned r; asm("cvt.rn.bf16x2.f32 %0, %1, %2;" : "=r"(r) : "f"(hi), "f"(lo));
    return r;
}
__device__ __forceinline__ void split1(float x, float& h, float& l) {
    h = __bfloat162float(__float2bfloat16(x));
    l = x - h;
}
__device__ __forceinline__ void mma16(float* d, const unsigned* a, const unsigned* b) {
    asm volatile("mma.sync.aligned.m16n8k16.row.col.f32.bf16.bf16.f32 "
        "{%0,%1,%2,%3}, {%4,%5,%6,%7}, {%8,%9}, {%0,%1,%2,%3};"
        : "+f"(d[0]), "+f"(d[1]), "+f"(d[2]), "+f"(d[3])
        : "r"(a[0]), "r"(a[1]), "r"(a[2]), "r"(a[3]), "r"(b[0]), "r"(b[1]));
}
__device__ __forceinline__ unsigned smem_u32(const void* p) {
    unsigned a;
    asm("{ .reg .u64 t; cvta.to.shared.u64 t, %1; cvt.u32.u64 %0, t; }"
        : "=r"(a) : "l"(p));
    return a;
}
__device__ __forceinline__ void cpa16(unsigned saddr, const void* g) {
    asm volatile("cp.async.cg.shared.global [%0], [%1], 16;"
                 :: "r"(saddr), "l"(g) : "memory");
}
__device__ __forceinline__ void ldsm4(unsigned* r, unsigned addr) {
    asm volatile("ldmatrix.sync.aligned.m8n8.x4.shared.b16 {%0,%1,%2,%3}, [%4];"
        : "=r"(r[0]), "=r"(r[1]), "=r"(r[2]), "=r"(r[3]) : "r"(addr));
}
#define CP_COMMIT() asm volatile("cp.async.commit_group;" ::: "memory")
#define CP_WAIT1()  asm volatile("cp.async.wait_group 1;" ::: "memory")
#define CP_WAIT0()  asm volatile("cp.async.wait_group 0;" ::: "memory")

// ===========================================================================
// Projection via Karatsuba complex (3 products, 9 bf16-split streams):
//   T1 = xr@Wr, T2 = xi@Wi, T3 = (xr+xi)@(Wr+Wi)
//   outR = T1 - T2 ;  outI = T3 - T1 - T2
// 512 threads, warp grid 4x4 (wm: 32 rows, wn: 16 cols), ldmatrix frag loads.
// A smem: 6 arrays [128][20] u32 (xr,xi,xs x h/l). B: 6 arrays [64][20].
// ===========================================================================
#define PJA_XRH 0
#define PJA_XRL 2560
#define PJA_XIH 5120
#define PJA_XIL 7680
#define PJA_XSH 10240
#define PJA_XSL 12800
#define PJB_WRH 15360
#define PJB_WIH 17920
#define PJB_WSH 20480
#define PJ_U32  23040

__global__ __launch_bounds__(512, 1) void proj_kernel(
    const float* __restrict__ xr,  const float* __restrict__ xi,
    const float* __restrict__ Wkr, const float* __restrict__ Wki,
    const float* __restrict__ Wqr, const float* __restrict__ Wqi,
    const float* __restrict__ Wvr, const float* __restrict__ Wvi)
{
    extern __shared__ unsigned smu[];
    const unsigned sbase = smem_u32(smu);

    const int tid  = threadIdx.x;
    const int lane = tid & 31;
    const int w    = tid >> 5;
    const int wm   = w >> 2;          // 0..3 : 32 rows
    const int wn   = w & 3;           // 0..3 : 16 cols
    const int g    = lane >> 2;
    const int kl   = lane & 3;

    const int rt  = blockIdx.x / 3;
    const int mat = blockIdx.x % 3;   // 0=K 1=Q 2=V
    const int m0  = rt * 128;

    const float* Wr_ = (mat==0)? Wkr : (mat==1)? Wqr : Wvr;
    const float* Wi_ = (mat==0)? Wki : (mat==1)? Wqi : Wvi;

    float T1[2][2][4], T2[2][2][4], T3[2][2][4];
    #pragma unroll
    for (int mt=0; mt<2; ++mt)
        #pragma unroll
        for (int nt=0; nt<2; ++nt)
            #pragma unroll
            for (int r=0; r<4; ++r) { T1[mt][nt][r]=0.f; T2[mt][nt][r]=0.f; T3[mt][nt][r]=0.f; }

    // staging ids
    const int a_row = tid >> 2;                 // 0..127
    const int a_q8  = (tid & 3) * 8;            // float col base
    const float* ar_src = xr + (size_t)(m0 + a_row)*C_ + a_q8;
    const float* ai_src = xi + (size_t)(m0 + a_row)*C_ + a_q8;
    const int b_n  = tid & 63;
    const int b_kq = tid >> 6;                  // 0..7, 2 pairs each

    // ldmatrix per-lane offsets (u32 units)
    const unsigned a_base = (unsigned)((wm*32 + (((lane>>3)&1)<<3) + (lane&7))*20
                                       + ((lane>>4)<<2));
    const unsigned b_base = (unsigned)(((lane>>4) ? 1280 : 0)
                                       + (wn*16 + (lane&7))*20 + (((lane>>3)&1)<<2));

    for (int c0 = 0; c0 < C_; c0 += 32) {
        __syncthreads();
        {   // ---- stage A: 8 floats of xr, xi; derive xs ----
            float4 r0 = *(const float4*)(ar_src + c0);
            float4 r1 = *(const float4*)(ar_src + c0 + 4);
            float4 i0 = *(const float4*)(ai_src + c0);
            float4 i1 = *(const float4*)(ai_src + c0 + 4);
            float a[8] = {r0.x,r0.y,r0.z,r0.w,r1.x,r1.y,r1.z,r1.w};
            float b[8] = {i0.x,i0.y,i0.z,i0.w,i1.x,i1.y,i1.z,i1.w};
            float h[8], l[8];
            const int ao = a_row*20 + (a_q8 >> 1);
            #pragma unroll
            for (int j=0;j<8;++j) split1(a[j],h[j],l[j]);
            *(uint4*)&smu[PJA_XRH + ao] = make_uint4(pkbf2(h[0],h[1]),pkbf2(h[2],h[3]),pkbf2(h[4],h[5]),pkbf2(h[6],h[7]));
            *(uint4*)&smu[PJA_XRL + ao] = make_uint4(pkbf2(l[0],l[1]),pkbf2(l[2],l[3]),pkbf2(l[4],l[5]),pkbf2(l[6],l[7]));
            #pragma unroll
            for (int j=0;j<8;++j) split1(b[j],h[j],l[j]);
            *(uint4*)&smu[PJA_XIH + ao] = make_uint4(pkbf2(h[0],h[1]),pkbf2(h[2],h[3]),pkbf2(h[4],h[5]),pkbf2(h[6],h[7]));
            *(uint4*)&smu[PJA_XIL + ao] = make_uint4(pkbf2(l[0],l[1]),pkbf2(l[2],l[3]),pkbf2(l[4],l[5]),pkbf2(l[6],l[7]));
            #pragma unroll
            for (int j=0;j<8;++j) split1(a[j]+b[j],h[j],l[j]);
            *(uint4*)&smu[PJA_XSH + ao] = make_uint4(pkbf2(h[0],h[1]),pkbf2(h[2],h[3]),pkbf2(h[4],h[5]),pkbf2(h[6],h[7]));
            *(uint4*)&smu[PJA_XSL + ao] = make_uint4(pkbf2(l[0],l[1]),pkbf2(l[2],l[3]),pkbf2(l[4],l[5]),pkbf2(l[6],l[7]));
        }
        {   // ---- stage B: 2 k-pairs of Wr, Wi; derive Ws ----
            #pragma unroll
            for (int j = 0; j < 2; ++j) {
                const int p = b_kq*2 + j;
                const size_t krow = (size_t)(c0 + 2*p);
                const float wr0 = Wr_[krow*H_ + b_n], wr1 = Wr_[krow*H_ + H_ + b_n];
                const float wi0 = Wi_[krow*H_ + b_n], wi1 = Wi_[krow*H_ + H_ + b_n];
                float h0,l0,h1,l1;
                split1(wr0,h0,l0); split1(wr1,h1,l1);
                smu[PJB_WRH +        b_n*20 + p] = pkbf2(h0,h1);
                smu[PJB_WRH + 1280 + b_n*20 + p] = pkbf2(l0,l1);
                split1(wi0,h0,l0); split1(wi1,h1,l1);
                smu[PJB_WIH +        b_n*20 + p] = pkbf2(h0,h1);
                smu[PJB_WIH + 1280 + b_n*20 + p] = pkbf2(l0,l1);
                split1(wr0+wi0,h0,l0); split1(wr1+wi1,h1,l1);
                smu[PJB_WSH +        b_n*20 + p] = pkbf2(h0,h1);
                smu[PJB_WSH + 1280 + b_n*20 + p] = pkbf2(l0,l1);
            }
        }
        __syncthreads();

        #pragma unroll
        for (int ks = 0; ks < 2; ++ks) {
            const unsigned pb = ks*8;
            #pragma unroll
            for (int mt = 0; mt < 2; ++mt) {
                const unsigned ao = a_base + mt*320 + pb;   // mt*16 rows * 20
                unsigned xrh_[4], xrl_[4], xih_[4], xil_[4], xsh_[4], xsl_[4];
                ldsm4(xrh_, sbase + (PJA_XRH + ao)*4u);
                ldsm4(xrl_, sbase + (PJA_XRL + ao)*4u);
                ldsm4(xih_, sbase + (PJA_XIH + ao)*4u);
                ldsm4(xil_, sbase + (PJA_XIL + ao)*4u);
                ldsm4(xsh_, sbase + (PJA_XSH + ao)*4u);
                ldsm4(xsl_, sbase + (PJA_XSL + ao)*4u);
                #pragma unroll
                for (int nt = 0; nt < 2; ++nt) {
                    const unsigned bo = b_base + nt*160 + pb;  // nt*8 rows * 20
                    unsigned wr_[4], wi_[4], ws_[4];
                    ldsm4(wr_, sbase + (PJB_WRH + bo)*4u);
                    ldsm4(wi_, sbase + (PJB_WIH + bo)*4u);
                    ldsm4(ws_, sbase + (PJB_WSH + bo)*4u);
                    mma16(T1[mt][nt], xrh_, wr_);
                    mma16(T1[mt][nt], xrh_, wr_+2);
                    mma16(T1[mt][nt], xrl_, wr_);
                    mma16(T2[mt][nt], xih_, wi_);
                    mma16(T2[mt][nt], xih_, wi_+2);
                    mma16(T2[mt][nt], xil_, wi_);
                    mma16(T3[mt][nt], xsh_, ws_);
                    mma16(T3[mt][nt], xsh_, ws_+2);
                    mma16(T3[mt][nt], xsl_, ws_);
                }
            }
        }
    }

    // ---- epilogue: combine + split + pack ----
    if (mat != 2) {
        unsigned *QRh, *QRl, *QIh, *QIl;
        if (mat == 0) { QRh=g_krh; QRl=g_krl; QIh=g_kih; QIl=g_kil; }
        else          { QRh=g_qrh; QRl=g_qrl; QIh=g_qih; QIl=g_qil; }
        #pragma unroll
        for (int mt = 0; mt < 2; ++mt) {
            const int rA = m0 + wm*32 + mt*16 + g;
            const int rB = rA + 8;
            #pragma unroll
            for (int nt = 0; nt < 2; ++nt) {
                const int pidx = wn*8 + nt*4 + kl;
                float r_[4], i_[4];
                #pragma unroll
                for (int r=0;r<4;++r) {
                    r_[r] = T1[mt][nt][r] - T2[mt][nt][r];
                    i_[r] = T3[mt][nt][r] - T1[mt][nt][r] - T2[mt][nt][r];
                }
                float h0,l0,h1,l1;
                split1(r_[0],h0,l0); split1(r_[1],h1,l1);
                QRh[(size_t)rA*32 + pidx] = pkbf2(h0,h1);
                QRl[(size_t)rA*32 + pidx] = pkbf2(l0,l1);
                split1(r_[2],h0,l0); split1(r_[3],h1,l1);
                QRh[(size_t)rB*32 + pidx] = pkbf2(h0,h1);
                QRl[(size_t)rB*32 + pidx] = pkbf2(l0,l1);
                split1(i_[0],h0,l0); split1(i_[1],h1,l1);
                QIh[(size_t)rA*32 + pidx] = pkbf2(h0,h1);
                QIl[(size_t)rA*32 + pidx] = pkbf2(l0,l1);
                split1(i_[2],h0,l0); split1(i_[3],h1,l1);
                QIh[(size_t)rB*32 + pidx] = pkbf2(h0,h1);
                QIl[(size_t)rB*32 + pidx] = pkbf2(l0,l1);
            }
        }
    } else {
        #pragma unroll
        for (int mt = 0; mt < 2; ++mt) {
            const int rA = m0 + wm*32 + mt*16 + g;    // parity(rA) == parity(g)
            const int rB = rA + 8;
            #pragma unroll
            for (int nt = 0; nt < 2; ++nt) {
                const int c0c = wn*16 + nt*8 + 2*kl;
                float r_[4], i_[4];
                #pragma unroll
                for (int r=0;r<4;++r) {
                    r_[r] = T1[mt][nt][r] - T2[mt][nt][r];
                    i_[r] = T3[mt][nt][r] - T1[mt][nt][r] - T2[mt][nt][r];
                }
                float pr[4], pi[4];
                #pragma unroll
                for (int r=0;r<4;++r) {
                    pr[r] = __shfl_xor_sync(~0u, r_[r], 4);
                    pi[r] = __shfl_xor_sync(~0u, i_[r], 4);
                }
                if ((g & 1) == 0) {
                    const size_t pA = (size_t)(rA >> 1);
                    const size_t pB = (size_t)(rB >> 1);
                    float h0,l0,h1,l1;
                    split1(r_[0],h0,l0); split1(pr[0],h1,l1);
                    g_vrh[(size_t)c0c*(M_/2) + pA] = pkbf2(h0,h1);
                    g_vrl[(size_t)c0c*(M_/2) + pA] = pkbf2(l0,l1);
                    split1(r_[1],h0,l0); split1(pr[1],h1,l1);
                    g_vrh[(size_t)(c0c+1)*(M_/2) + pA] = pkbf2(h0,h1);
                    g_vrl[(size_t)(c0c+1)*(M_/2) + pA] = pkbf2(l0,l1);
                    split1(r_[2],h0,l0); split1(pr[2],h1,l1);
                    g_vrh[(size_t)c0c*(M_/2) + pB] = pkbf2(h0,h1);
                    g_vrl[(size_t)c0c*(M_/2) + pB] = pkbf2(l0,l1);
                    split1(r_[3],h0,l0); split1(pr[3],h1,l1);
                    g_vrh[(size_t)(c0c+1)*(M_/2) + pB] = pkbf2(h0,h1);
                    g_vrl[(size_t)(c0c+1)*(M_/2) + pB] = pkbf2(l0,l1);
                    split1(i_[0],h0,l0); split1(pi[0],h1,l1);
                    g_vih[(size_t)c0c*(M_/2) + pA] = pkbf2(h0,h1);
                    g_vil[(size_t)c0c*(M_/2) + pA] = pkbf2(l0,l1);
                    split1(i_[1],h0,l0); split1(pi[1],h1,l1);
                    g_vih[(size_t)(c0c+1)*(M_/2) + pA] = pkbf2(h0,h1);
                    g_vil[(size_t)(c0c+1)*(M_/2) + pA] = pkbf2(l0,l1);
                    split1(i_[2],h0,l0); split1(pi[2],h1,l1);
                    g_vih[(size_t)c0c*(M_/2) + pB] = pkbf2(h0,h1);
                    g_vil[(size_t)c0c*(M_/2) + pB] = pkbf2(l0,l1);
                    split1(i_[3],h0,l0); split1(pi[3],h1,l1);
                    g_vih[(size_t)(c0c+1)*(M_/2) + pB] = pkbf2(h0,h1);
                    g_vil[(size_t)(c0c+1)*(M_/2) + pB] = pkbf2(l0,l1);
                }
            }
        }
    }
}

// ===========================================================================
// Flash attention (unchanged R15): causal-paired, plain-exp, ldmatrix.
// ===========================================================================
#define AQH 0
#define AQL 4608
#define APH 9216
#define APL 11520
#define AKV 13824
#define KV_STAGE 18432
#define AT_U32 (13824 + 2*18432)
#define AT_BYTES ((AT_U32 + 256)*4)

__global__ __launch_bounds__(512, 1) void attn_kernel(float* __restrict__ out)
{
    extern __shared__ unsigned smu[];
    float* reds = (float*)(smu + AT_U32);
    const unsigned sbase = smem_u32(smu);

    const int b    = blockIdx.y;
    const int pp   = blockIdx.x;
    const int tid  = threadIdx.x;
    const int lane = tid & 31;
    const int w    = tid >> 5;
    const int wm   = w >> 2;
    const int wn   = w & 3;
    const int g    = lane >> 2;
    const int kl   = lane & 3;
    const int lr0 = wm*16 + g, lr1 = lr0 + 8;

    const int sm_row = tid >> 3;
    const int sm_qq  = (tid & 7)*4;

    const unsigned a_off = (unsigned)((wm*16 + (((lane>>3)&1)<<3) + (lane&7))*36
                                      + ((lane>>4)<<2));
    const unsigned b_off = (unsigned)(((lane>>4) ? 4608 : 0)
                                      + (lane&7)*36 + (((lane>>3)&1)<<2));

    #pragma unroll 1
    for (int pass = 0; pass < 2; ++pass) {
        const int qt = pass ? pp : (31 - pp);
        const int qbase = b*T_ + qt*64;

        {
            const int kb_row = b*T_;
            const unsigned so = sbase + (unsigned)(AKV + sm_row*36 + sm_qq)*4u;
            const size_t kb = (size_t)(kb_row + sm_row)*32 + sm_qq;
            cpa16(so + 0*2304*4, &g_krh[kb]);
            cpa16(so + 1*2304*4, &g_kih[kb]);
            cpa16(so + 2*2304*4, &g_krl[kb]);
            cpa16(so + 3*2304*4, &g_kil[kb]);
            const size_t vb = (size_t)sm_row*(M_/2) + (size_t)(kb_row >> 1) + sm_qq;
            cpa16(so + 4*2304*4, &g_vrh[vb]);
            cpa16(so + 5*2304*4, &g_vih[vb]);
            cpa16(so + 6*2304*4, &g_vrl[vb]);
            cpa16(so + 7*2304*4, &g_vil[vb]);
            CP_COMMIT();
        }
        {
            const size_t base = (size_t)(qbase + sm_row)*32 + sm_qq;
            *(uint4*)&smu[AQH +        sm_row*36 + sm_qq] = *(const uint4*)&g_qrh[base];
            *(uint4*)&smu[AQH + 2304 + sm_row*36 + sm_qq] = *(const uint4*)&g_qih[base];
            *(uint4*)&smu[AQL +        sm_row*36 + sm_qq] = *(const uint4*)&g_qrl[base];
            *(uint4*)&smu[AQL + 2304 + sm_row*36 + sm_qq] = *(const uint4*)&g_qil[base];
        }

        float Or[2][4], Oi[2][4];
        float rs0 = 0.f, rs1 = 0.f;
        #pragma unroll
        for (int nt=0;nt<2;nt++)
            #pragma unroll
            for (int r=0;r<4;r++) { Or[nt][r]=0.f; Oi[nt][r]=0.f; }

        for (int kt = 0; kt <= qt; ++kt) {
            const int cur = kt & 1;
            __syncthreads();
            if (kt < qt) {
                const int kb_row = b*T_ + (kt+1)*64;
                const unsigned so = sbase
                    + (unsigned)(AKV + (1-cur)*KV_STAGE + sm_row*36 + sm_qq)*4u;
                const size_t kb = (size_t)(kb_row + sm_row)*32 + sm_qq;
                cpa16(so + 0*2304*4, &g_krh[kb]);
                cpa16(so + 1*2304*4, &g_kih[kb]);
                cpa16(so + 2*2304*4, &g_krl[kb]);
                cpa16(so + 3*2304*4, &g_kil[kb]);
                const size_t vb = (size_t)sm_row*(M_/2) + (size_t)(kb_row >> 1) + sm_qq;
                cpa16(so + 4*2304*4, &g_vrh[vb]);
                cpa16(so + 5*2304*4, &g_vih[vb]);
                cpa16(so + 6*2304*4, &g_vrl[vb]);
                cpa16(so + 7*2304*4, &g_vil[vb]);
                CP_COMMIT();
                CP_WAIT1();
            } else {
                CP_WAIT0();
            }
            __syncthreads();

            const unsigned KH = AKV + cur*KV_STAGE;
            const unsigned VH = KH + 9216;

            float Sr[2][4], Si[2][4];
            #pragma unroll
            for (int nt=0;nt<2;nt++)
                #pragma unroll
                for (int r=0;r<4;r++) { Sr[nt][r]=0.f; Si[nt][r]=0.f; }

            #pragma unroll
            for (int ks = 0; ks < 4; ++ks) {
                const unsigned pb = ks*8;
                unsigned qr_[4], ql_[4], qi_[4], qj_[4];
                ldsm4(qr_, sbase + (AQH +        a_off + pb)*4u);
                ldsm4(ql_, sbase + (AQL +        a_off + pb)*4u);
                ldsm4(qi_, sbase + (AQH + 2304 + a_off + pb)*4u);
                ldsm4(qj_, sbase + (AQL + 2304 + a_off + pb)*4u);
                #pragma unroll
                for (int nt = 0; nt < 2; ++nt) {
                    const unsigned n0b = (unsigned)((wn*16 + nt*8)*36);
                    unsigned kr_[4], ki_[4], ni_[4];
                    ldsm4(kr_, sbase + (KH +        n0b + b_off + pb)*4u);
                    ldsm4(ki_, sbase + (KH + 2304 + n0b + b_off + pb)*4u);
                    #pragma unroll
                    for (int r=0;r<4;++r) ni_[r] = ki_[r] ^ 0x80008000u;
                    mma16(Sr[nt], qr_, kr_);
                    mma16(Sr[nt], qr_, kr_+2);
                    mma16(Sr[nt], ql_, kr_);
                    mma16(Sr[nt], qi_, ki_);
                    mma16(Sr[nt], qi_, ki_+2);
                    mma16(Sr[nt], qj_, ki_);
                    mma16(Si[nt], qi_, kr_);
                    mma16(Si[nt], qi_, kr_+2);
                    mma16(Si[nt], qj_, kr_);
                    mma16(Si[nt], qr_, ni_);
                    mma16(Si[nt], qr_, ni_+2);
                    mma16(Si[nt], ql_, ni_);
                }
            }

            #pragma unroll
            for (int nt = 0; nt < 2; ++nt) {
                float e[4];
                #pragma unroll
                for (int r = 0; r < 4; ++r) {
                    const float sr = Sr[nt][r], si = Si[nt][r];
                    const float m2 = fmaf(sr, sr, fmaf(si, si, 1e-4f));
                    const float v = m2 * rsqrtf(m2) * 0.125f;
                    const int colg = kt*64 + wn*16 + nt*8 + 2*kl + (r&1);
                    const int rowg = qt*64 + ((r<2) ? lr0 : lr1);
                    e[r] = (colg <= rowg) ? __expf(v) : 0.f;
                }
                rs0 += e[0] + e[1];
                rs1 += e[2] + e[3];
                const int pidx = wn*8 + nt*4 + kl;
                float h0,l0,h1,l1,h2,l2,h3,l3;
                split1(e[0],h0,l0); split1(e[1],h1,l1);
                split1(e[2],h2,l2); split1(e[3],h3,l3);
                smu[APH + lr0*36 + pidx] = pkbf2(h0,h1);
                smu[APL + lr0*36 + pidx] = pkbf2(l0,l1);
                smu[APH + lr1*36 + pidx] = pkbf2(h2,h3);
                smu[APL + lr1*36 + pidx] = pkbf2(l2,l3);
            }
            __syncthreads();

            #pragma unroll
            for (int ks = 0; ks < 4; ++ks) {
                const unsigned pb = ks*8;
                unsigned ph_[4], pl_[4];
                ldsm4(ph_, sbase + (APH + a_off + pb)*4u);
                ldsm4(pl_, sbase + (APL + a_off + pb)*4u);
                #pragma unroll
                for (int nt = 0; nt < 2; ++nt) {
                    const unsigned n0b = (unsigned)((wn*16 + nt*8)*36);
                    unsigned vr_[4], vi_[4];
                    ldsm4(vr_, sbase + (VH +        n0b + b_off + pb)*4u);
                    ldsm4(vi_, sbase + (VH + 2304 + n0b + b_off + pb)*4u);
                    mma16(Or[nt], ph_, vr_);
                    mma16(Or[nt], ph_, vr_+2);
                    mma16(Or[nt], pl_, vr_);
                    mma16(Oi[nt], ph_, vi_);
                    mma16(Oi[nt], ph_, vi_+2);
                    mma16(Oi[nt], pl_, vi_);
                }
            }
        }

        rs0 += __shfl_xor_sync(~0u, rs0, 1);
        rs0 += __shfl_xor_sync(~0u, rs0, 2);
        rs1 += __shfl_xor_sync(~0u, rs1, 1);
        rs1 += __shfl_xor_sync(~0u, rs1, 2);
        __syncthreads();
        if (kl == 0) { reds[wn*64 + lr0] = rs0; reds[wn*64 + lr1] = rs1; }
        __syncthreads();

        const float inv0 = 1.f / (reds[lr0] + reds[64+lr0] + reds[128+lr0] + reds[192+lr0]);
        const float inv1 = 1.f / (reds[lr1] + reds[64+lr1] + reds[128+lr1] + reds[192+lr1]);
        #pragma unroll
        for (int nt = 0; nt < 2; ++nt) {
            const int h0 = wn*16 + nt*8 + 2*kl;
            const size_t rA = (size_t)(qbase + lr0);
            const size_t rB = (size_t)(qbase + lr1);
            *(float2*)(out + rA*H_ + h0) = make_float2(Or[nt][0]*inv0, Or[nt][1]*inv0);
            *(float2*)(out + rB*H_ + h0) = make_float2(Or[nt][2]*inv1, Or[nt][3]*inv1);
            *(float2*)(out + (size_t)M_*H_ + rA*H_ + h0) = make_float2(Oi[nt][0]*inv0, Oi[nt][1]*inv0);
            *(float2*)(out + (size_t)M_*H_ + rB*H_ + h0) = make_float2(Oi[nt][2]*inv1, Oi[nt][3]*inv1);
        }
        __syncthreads();
    }
}

// ---------------------------------------------------------------------------
extern "C" void kernel_launch(void* const* d_in, const int* in_sizes, int n_in,
                              void* d_out, int out_size)
{
    const float* xr  = (const float*)d_in[0];
    const float* xi  = (const float*)d_in[1];
    const float* Wkr = (const float*)d_in[2];
    const float* Wki = (const float*)d_in[3];
    const float* Wqr = (const float*)d_in[4];
    const float* Wqi = (const float*)d_in[5];
    const float* Wvr = (const float*)d_in[6];
    const float* Wvi = (const float*)d_in[7];

    cudaFuncSetAttribute(proj_kernel,
        cudaFuncAttributeMaxDynamicSharedMemorySize, PJ_U32*4);
    cudaFuncSetAttribute(attn_kernel,
        cudaFuncAttributeMaxDynamicSharedMemorySize, AT_BYTES);

    proj_kernel<<<(M_/128)*3, 512, PJ_U32*4>>>(xr, xi, Wkr, Wki, Wqr, Wqi, Wvr, Wvi);

    dim3 ag(T_/128, B_);   // 16 pairs x 8 batches
    attn_kernel<<<ag, 512, AT_BYTES>>>((float*)d_out);
}